// round 11
// baseline (speedup 1.0000x reference)
#include <cuda_runtime.h>
#include <cstdint>

#define B_ 256
#define T_ 512
#define C_ 256
#define L_ 64

__device__ float g_loss[B_];
__device__ unsigned int g_ctr = 0;

__device__ __forceinline__ uint32_t smem_u32(const void* p) {
  return (uint32_t)__cvta_generic_to_shared(p);
}

// ---------------------------------------------------------------------------
// Fused CTC kernel: one block per batch row. 9 warps:
//   warps 0-7 (producers): cp.async raw logits rows into a 4-phase smem ring
//     (fire-and-forget, 3-phase latency cover), then softmax from smem and
//     write the compressed prob row [eb*256 | p_odd*mask*256] for the consumer.
//   warp 8 (consumer): linear-domain CTC recurrence (4 states/lane + s=128 on
//     lane 31, 1 shfl/step, 2^8 pre-scale, pipelined power-of-2 renorm).
// Last block folds the batch mean in via atomic ticket (replay-safe reset).
// ---------------------------------------------------------------------------
__global__ void __launch_bounds__(288) ctc_fused_kernel(
    const float* __restrict__ logits,
    const int* __restrict__ targets,
    const int* __restrict__ input_lengths,
    const int* __restrict__ target_lengths,
    float* __restrict__ out) {
  __shared__ float raw[4][8][C_];      // 32 KB raw logits ring
  __shared__ float ring[2][8][68];     // compressed [eb, pad*3, p1,p3,...,p127]
  __shared__ float scratch[8][C_];     // per-producer-warp exp scratch
  __shared__ int   stg[L_];
  __shared__ float shf[132];

  int b = blockIdx.x;
  int tid = threadIdx.x;
  int wid = tid >> 5, lane = tid & 31;
  int len = input_lengths[b];
  int tl  = target_lengths[b];
  int Sb  = 2 * tl + 1;

  if (tid < L_) stg[tid] = targets[b * L_ + tid];
  __syncthreads();                                    // barrier 1

  const float* lg = logits + (size_t)b * T_ * C_;

  if (wid < 8) {
    // ---------------- producers ----------------
    int t0l = stg[2 * lane], t1l = stg[2 * lane + 1];
    float c1 = (4 * lane + 1 < Sb) ? 256.f : 0.f;
    float c3 = (4 * lane + 3 < Sb) ? 256.f : 0.f;
    float* scr = scratch[wid];

#define ISSUE(PH)                                                          \
    do {                                                                   \
      int r_ = (PH) * 8 + wid; r_ = r_ < T_ ? r_ : T_ - 1;                 \
      const float* s_ = lg + (size_t)r_ * C_;                              \
      uint32_t d_ = smem_u32(&raw[(PH) & 3][wid][0]);                      \
      asm volatile("cp.async.cg.shared.global [%0], [%1], 16;"             \
                   :: "r"(d_ + lane * 16), "l"(s_ + lane * 4));            \
      asm volatile("cp.async.cg.shared.global [%0], [%1], 16;"             \
                   :: "r"(d_ + (lane + 32) * 16), "l"(s_ + (lane + 32) * 4)); \
      asm volatile("cp.async.commit_group;");                              \
    } while (0)

#define PRODUCE(PH)                                                        \
    do {                                                                   \
      const float* rrow = raw[(PH) & 3][wid];                              \
      float4 vA = ((const float4*)rrow)[lane];                             \
      float4 vB = ((const float4*)rrow)[lane + 32];                        \
      float4 eA, eB;                                                       \
      eA.x = __expf(vA.x); eA.y = __expf(vA.y);                            \
      eA.z = __expf(vA.z); eA.w = __expf(vA.w);                            \
      eB.x = __expf(vB.x); eB.y = __expf(vB.y);                            \
      eB.z = __expf(vB.z); eB.w = __expf(vB.w);                            \
      float s = ((eA.x + eA.y) + (eA.z + eA.w)) +                          \
                ((eB.x + eB.y) + (eB.z + eB.w));                           \
      _Pragma("unroll")                                                    \
      for (int o = 16; o; o >>= 1) s += __shfl_xor_sync(0xffffffffu, s, o);\
      float inv = __frcp_rn(s);                                            \
      ((float4*)scr)[lane]      = eA;                                      \
      ((float4*)scr)[lane + 32] = eB;                                      \
      __syncwarp();                                                        \
      float2 o2;                                                           \
      o2.x = scr[t0l] * inv * c1;                                          \
      o2.y = scr[t1l] * inv * c3;                                          \
      float* slot = ring[(PH) & 1][wid];                                   \
      ((float2*)(slot + 4))[lane] = o2;                                    \
      if (lane == 0) slot[0] = scr[0] * inv * 256.f;                       \
      __syncwarp();                                                        \
    } while (0)

    ISSUE(0); ISSUE(1); ISSUE(2); ISSUE(3);
    asm volatile("cp.async.wait_group 3;");
    PRODUCE(0);
    __syncthreads();                                  // barrier 2

    for (int p = 0; p < 63; p++) {
      ISSUE(p + 4);                                   // writes slot (p)&3: dead
      asm volatile("cp.async.wait_group 3;");
      PRODUCE(p + 1);
      __syncthreads();
    }
    asm volatile("cp.async.wait_group 0;");
#undef ISSUE
#undef PRODUCE
  } else {
    // ---------------- consumer (warp 8) ----------------
    int t0l = stg[2 * lane], t1l = stg[2 * lane + 1];
    float skip1 = 0.f, skip3 = (t1l != t0l) ? 1.f : 0.f;
    if (lane > 0) skip1 = (t0l != stg[2 * lane - 1]) ? 1.f : 0.f;
    float c0 = (lane > 0 && 4 * lane < Sb) ? 1.f : 0.f;

    float a0 = 0.f, a1 = 0.f, a2 = 0.f, a3 = 0.f, a4 = 0.f;
    int e_total = 0, epend = 0;
    float fpend = 1.f;

#define CTC_STEP(EB, PL)                                                   \
    do {                                                                   \
      float u1 = __shfl_up_sync(0xffffffffu, a3, 1) * c0;                  \
      float n0 = (a0 + u1) * (EB);                                         \
      float n1 = fmaf(skip1, u1, a1 + a0) * (PL).x;                        \
      float n2 = (a2 + a1) * (EB);                                         \
      float n3 = fmaf(skip3, a1, a3 + a2) * (PL).y;                        \
      float n4 = (a4 + a3) * (EB);                                         \
      a0 = n0; a1 = n1; a2 = n2; a3 = n3; a4 = n4;                         \
    } while (0)

#define CTC_RENORM_PIPE()                                                  \
    do {                                                                   \
      a0 *= fpend; a1 *= fpend; a2 *= fpend; a3 *= fpend; a4 *= fpend;     \
      e_total += epend;                                                    \
      float lm = fmaxf(fmaxf(a0, a1), fmaxf(fmaxf(a2, a3), a4));           \
      unsigned mb = __reduce_max_sync(0xffffffffu, __float_as_uint(lm));   \
      epend = (mb != 0u) ? ((int)(mb >> 23) - 127) : 0;                    \
      fpend = __int_as_float((127 - epend) << 23);                         \
    } while (0)

#define CTC_PHASE(P)                                                       \
    do {                                                                   \
      float(*buf)[68] = ring[(P) & 1];                                     \
      float  ebv[8];                                                       \
      float2 plv[8];                                                       \
      _Pragma("unroll")                                                    \
      for (int u = 0; u < 8; u++) {                                        \
        ebv[u] = buf[u][0];                                                \
        plv[u] = ((float2*)(buf[u] + 4))[lane];                            \
      }                                                                    \
      _Pragma("unroll")                                                    \
      for (int u = 0; u < 8; u++) {                                        \
        int tt = (P) * 8 + u;                                              \
        if (tt == 0) {                                                     \
          if (lane == 0) {                                                 \
            a0 = ebv[0] * (1.f / 256.f);                                   \
            a1 = plv[0].x * (1.f / 256.f);                                 \
          }                                                                \
        } else if (tt < len) {                                             \
          CTC_STEP(ebv[u], plv[u]);                                        \
          if ((tt & 3) == 3) CTC_RENORM_PIPE();                            \
        }                                                                  \
      }                                                                    \
    } while (0)

    __syncthreads();                                  // barrier 2 (ring0 ready)
    for (int p = 0; p < 63; p++) {
      CTC_PHASE(p);
      __syncthreads();
    }
    CTC_PHASE(63);

    // per-row loss
    shf[4 * lane + 0] = a0;
    shf[4 * lane + 1] = a1;
    shf[4 * lane + 2] = a2;
    shf[4 * lane + 3] = a3;
    if (lane == 31) shf[128] = a4;
    __syncwarp();
    if (lane == 0) {
      float ssum = shf[2 * tl] + shf[2 * tl - 1];
      // a_true = a_stored * 2^(e_total - 8*(len-1))
      float loss = -(logf(ssum) +
                     (float)(e_total - 8 * (len - 1)) * 0.69314718055994530942f);
      if (!isfinite(loss) || loss > 1e20f) loss = 0.f;   // zero_infinity
      g_loss[b] = loss / (float)tl;
    }

    // fold the batch mean into the last-arriving block (replay-safe)
    __threadfence();
    unsigned tkt = 0;
    if (lane == 0) tkt = atomicAdd(&g_ctr, 1u);
    tkt = __shfl_sync(0xffffffffu, tkt, 0);
    if (tkt == B_ - 1) {
      __threadfence();
      float v = 0.f;
      #pragma unroll
      for (int j = 0; j < 8; j++) v += __ldcg(&g_loss[lane * 8 + j]);
      #pragma unroll
      for (int o = 16; o; o >>= 1) v += __shfl_xor_sync(0xffffffffu, v, o);
      if (lane == 0) {
        *out = v * (1.0f / (float)B_);
        atomicExch(&g_ctr, 0u);                        // reset for graph replay
      }
    }
#undef CTC_STEP
#undef CTC_RENORM_PIPE
#undef CTC_PHASE
  }
}

extern "C" void kernel_launch(void* const* d_in, const int* in_sizes, int n_in,
                              void* d_out, int out_size) {
  const float* logits         = (const float*)d_in[0];
  const int*   targets        = (const int*)d_in[1];
  const int*   input_lengths  = (const int*)d_in[2];
  const int*   target_lengths = (const int*)d_in[3];
  (void)in_sizes; (void)n_in; (void)out_size;

  ctc_fused_kernel<<<B_, 288>>>(logits, targets, input_lengths, target_lengths,
                                (float*)d_out);
}

// round 12
// speedup vs baseline: 1.1609x; 1.1609x over previous
#include <cuda_runtime.h>
#include <cstdint>

#define B_ 256
#define T_ 512
#define C_ 256
#define L_ 64

__device__ float g_loss[B_];
__device__ unsigned int g_ctr = 0;

// ---------------------------------------------------------------------------
// Fused CTC kernel: one block per batch row. 9 warps:
//   warps 0-7 (producers): direct LDG->register staging with TWO-phase
//     lookahead (statically named buffers, loop unrolled x2 so ring parity and
//     buffer names are compile-time); softmax; write compressed prob row
//     [eb*256 | p_odd*mask*256] into the 2-slot smem ring.
//   warp 8 (consumer): linear-domain CTC recurrence (4 states/lane + s=128 on
//     lane 31, 1 shfl/step, 2^8 pre-scale, pipelined power-of-2 renorm).
// Batch mean folded in via atomic ticket (replay-safe reset).
// ---------------------------------------------------------------------------
__global__ void __launch_bounds__(288) ctc_fused_kernel(
    const float* __restrict__ logits,
    const int* __restrict__ targets,
    const int* __restrict__ input_lengths,
    const int* __restrict__ target_lengths,
    float* __restrict__ out) {
  __shared__ float ring[2][8][68];     // compressed [eb, pad*3, p1,p3,...,p127]
  __shared__ float scratch[8][C_];     // per-producer-warp exp scratch
  __shared__ int   stg[L_];
  __shared__ float shf[132];

  int b = blockIdx.x;
  int tid = threadIdx.x;
  int wid = tid >> 5, lane = tid & 31;
  int len = input_lengths[b];
  int tl  = target_lengths[b];
  int Sb  = 2 * tl + 1;

  if (tid < L_) stg[tid] = targets[b * L_ + tid];
  __syncthreads();                                    // barrier 1

  const float* lg = logits + (size_t)b * T_ * C_;

  if (wid < 8) {
    // ---------------- producers ----------------
    int t0l = stg[2 * lane], t1l = stg[2 * lane + 1];
    float c1m = (4 * lane + 1 < Sb) ? 256.f : 0.f;
    float c3m = (4 * lane + 3 < Sb) ? 256.f : 0.f;
    float* scr = scratch[wid];

#define LOADPH(PH, RA, RB)                                                 \
    do {                                                                   \
      int r_ = (PH) * 8 + wid; r_ = r_ < T_ ? r_ : T_ - 1;                 \
      const float4* p_ = (const float4*)(lg + (size_t)r_ * C_);            \
      (RA) = p_[lane]; (RB) = p_[lane + 32];                               \
    } while (0)

#define PRODUCE(VA, VB, SLOT)                                              \
    do {                                                                   \
      float4 eA, eB;                                                       \
      eA.x = __expf((VA).x); eA.y = __expf((VA).y);                        \
      eA.z = __expf((VA).z); eA.w = __expf((VA).w);                        \
      eB.x = __expf((VB).x); eB.y = __expf((VB).y);                        \
      eB.z = __expf((VB).z); eB.w = __expf((VB).w);                        \
      float s = ((eA.x + eA.y) + (eA.z + eA.w)) +                          \
                ((eB.x + eB.y) + (eB.z + eB.w));                           \
      _Pragma("unroll")                                                    \
      for (int o = 16; o; o >>= 1) s += __shfl_xor_sync(0xffffffffu, s, o);\
      float inv = __frcp_rn(s);                                            \
      ((float4*)scr)[lane]      = eA;                                      \
      ((float4*)scr)[lane + 32] = eB;                                      \
      __syncwarp();                                                        \
      float2 o2;                                                           \
      o2.x = scr[t0l] * inv * c1m;                                         \
      o2.y = scr[t1l] * inv * c3m;                                         \
      ((float2*)((SLOT) + 4))[lane] = o2;                                  \
      if (lane == 0) (SLOT)[0] = scr[0] * inv * 256.f;                     \
      __syncwarp();                                                        \
    } while (0)

    // preamble: phase 0 direct; stage phases 1 (c0) and 2 (c1)
    float4 c0A, c0B, c1A, c1B;
    {
      float4 aA, aB;
      LOADPH(0, aA, aB);
      LOADPH(1, c0A, c0B);
      LOADPH(2, c1A, c1B);
      PRODUCE(aA, aB, ring[0][wid]);
    }
    __syncthreads();                                  // barrier 2 (ring0 ready)

    // 31 pairs: produce odd phase 2p+1 from c0 (-> ring[1]),
    //           even phase 2p+2 from c1 (-> ring[0]); stage 2 ahead.
    for (int p = 0; p < 31; p++) {
      float4 nA, nB;
      LOADPH(2 * p + 3, nA, nB);
      PRODUCE(c0A, c0B, ring[1][wid]);
      c0A = nA; c0B = nB;
      __syncthreads();
      LOADPH(2 * p + 4, nA, nB);
      PRODUCE(c1A, c1B, ring[0][wid]);
      c1A = nA; c1B = nB;
      __syncthreads();
    }
    // phase 63 (odd -> ring[1]) from c0
    PRODUCE(c0A, c0B, ring[1][wid]);
    __syncthreads();
#undef LOADPH
#undef PRODUCE
  } else {
    // ---------------- consumer (warp 8) ----------------
    int t0l = stg[2 * lane], t1l = stg[2 * lane + 1];
    float skip1 = 0.f, skip3 = (t1l != t0l) ? 1.f : 0.f;
    if (lane > 0) skip1 = (t0l != stg[2 * lane - 1]) ? 1.f : 0.f;
    float c0 = (lane > 0 && 4 * lane < Sb) ? 1.f : 0.f;

    float a0 = 0.f, a1 = 0.f, a2 = 0.f, a3 = 0.f, a4 = 0.f;
    int e_total = 0, epend = 0;
    float fpend = 1.f;

#define CTC_STEP(EB, PL)                                                   \
    do {                                                                   \
      float u1 = __shfl_up_sync(0xffffffffu, a3, 1) * c0;                  \
      float n0 = (a0 + u1) * (EB);                                         \
      float n1 = fmaf(skip1, u1, a1 + a0) * (PL).x;                        \
      float n2 = (a2 + a1) * (EB);                                         \
      float n3 = fmaf(skip3, a1, a3 + a2) * (PL).y;                        \
      float n4 = (a4 + a3) * (EB);                                         \
      a0 = n0; a1 = n1; a2 = n2; a3 = n3; a4 = n4;                         \
    } while (0)

#define CTC_RENORM_PIPE()                                                  \
    do {                                                                   \
      a0 *= fpend; a1 *= fpend; a2 *= fpend; a3 *= fpend; a4 *= fpend;     \
      e_total += epend;                                                    \
      float lm = fmaxf(fmaxf(a0, a1), fmaxf(fmaxf(a2, a3), a4));           \
      unsigned mb = __reduce_max_sync(0xffffffffu, __float_as_uint(lm));   \
      epend = (mb != 0u) ? ((int)(mb >> 23) - 127) : 0;                    \
      fpend = __int_as_float((127 - epend) << 23);                         \
    } while (0)

#define CTC_PHASE(P, PAR)                                                  \
    do {                                                                   \
      float(*buf)[68] = ring[(PAR)];                                       \
      float  ebv[8];                                                       \
      float2 plv[8];                                                       \
      _Pragma("unroll")                                                    \
      for (int u = 0; u < 8; u++) {                                        \
        ebv[u] = buf[u][0];                                                \
        plv[u] = ((float2*)(buf[u] + 4))[lane];                            \
      }                                                                    \
      _Pragma("unroll")                                                    \
      for (int u = 0; u < 8; u++) {                                        \
        int tt = (P) * 8 + u;                                              \
        if (tt == 0) {                                                     \
          if (lane == 0) {                                                 \
            a0 = ebv[0] * (1.f / 256.f);                                   \
            a1 = plv[0].x * (1.f / 256.f);                                 \
          }                                                                \
        } else if (tt < len) {                                             \
          CTC_STEP(ebv[u], plv[u]);                                        \
          if ((tt & 3) == 3) CTC_RENORM_PIPE();                            \
        }                                                                  \
      }                                                                    \
    } while (0)

    __syncthreads();                                  // barrier 2 (ring0 ready)
    CTC_PHASE(0, 0);
    __syncthreads();
    for (int p = 0; p < 31; p++) {
      CTC_PHASE(2 * p + 1, 1);
      __syncthreads();
      CTC_PHASE(2 * p + 2, 0);
      __syncthreads();
    }
    CTC_PHASE(63, 1);

    // per-row loss
    shf[4 * lane + 0] = a0;
    shf[4 * lane + 1] = a1;
    shf[4 * lane + 2] = a2;
    shf[4 * lane + 3] = a3;
    if (lane == 31) shf[128] = a4;
    __syncwarp();
    if (lane == 0) {
      float ssum = shf[2 * tl] + shf[2 * tl - 1];
      // a_true = a_stored * 2^(e_total - 8*(len-1))
      float loss = -(logf(ssum) +
                     (float)(e_total - 8 * (len - 1)) * 0.69314718055994530942f);
      if (!isfinite(loss) || loss > 1e20f) loss = 0.f;   // zero_infinity
      g_loss[b] = loss / (float)tl;
    }

    // fold the batch mean into the last-arriving block (replay-safe)
    __threadfence();
    unsigned tkt = 0;
    if (lane == 0) tkt = atomicAdd(&g_ctr, 1u);
    tkt = __shfl_sync(0xffffffffu, tkt, 0);
    if (tkt == B_ - 1) {
      __threadfence();
      float v = 0.f;
      #pragma unroll
      for (int j = 0; j < 8; j++) v += __ldcg(&g_loss[lane * 8 + j]);
      #pragma unroll
      for (int o = 16; o; o >>= 1) v += __shfl_xor_sync(0xffffffffu, v, o);
      if (lane == 0) {
        *out = v * (1.0f / (float)B_);
        atomicExch(&g_ctr, 0u);                        // reset for graph replay
      }
    }
#undef CTC_STEP
#undef CTC_RENORM_PIPE
#undef CTC_PHASE
  }
}

extern "C" void kernel_launch(void* const* d_in, const int* in_sizes, int n_in,
                              void* d_out, int out_size) {
  const float* logits         = (const float*)d_in[0];
  const int*   targets        = (const int*)d_in[1];
  const int*   input_lengths  = (const int*)d_in[2];
  const int*   target_lengths = (const int*)d_in[3];
  (void)in_sizes; (void)n_in; (void)out_size;

  ctc_fused_kernel<<<B_, 288>>>(logits, targets, input_lengths, target_lengths,
                                (float*)d_out);
}

// round 13
// speedup vs baseline: 1.2076x; 1.0402x over previous
#include <cuda_runtime.h>
#include <cstdint>

#define B_ 256
#define T_ 512
#define C_ 256
#define L_ 64

__device__ float g_loss[B_];
__device__ unsigned int g_ctr = 0;

// Named-barrier helpers (count = all 288 threads; producers 256 + consumer 32).
// Producer arrives FULL (non-blocking), consumer syncs FULL; consumer arrives
// EMPTY, producers sync EMPTY. PTX-documented producer/consumer pattern.
#define BAR_SYNC(ID)   asm volatile("bar.sync %0, 288;"   :: "n"(ID) : "memory")
#define BAR_ARRIVE(ID) asm volatile("bar.arrive %0, 288;" :: "n"(ID) : "memory")
#define FULL0 1
#define FULL1 2
#define FULL2 3
#define FULL3 4
#define EMPTY0 5
#define EMPTY1 6
#define EMPTY2 7
#define EMPTY3 8

// ---------------------------------------------------------------------------
// Fused CTC kernel: one block per batch row, warp-specialized with DECOUPLED
// producer/consumer synchronization (4-slot ring + named barriers), so
// producers run up to 3 phases ahead instead of lockstep per-phase max().
//   warps 0-7: LDG->reg 2-phase lookahead, softmax, write compressed row
//              [eb*256 | p_odd*mask*256] to ring slot, bar.arrive(full).
//   warp 8:    CTC recurrence (4 states/lane + s=128 on lane 31, 1 shfl/step,
//              2^8 pre-scale, pipelined power-of-2 renorm), bar.arrive(empty).
// Batch mean folded in via atomic ticket (replay-safe reset).
// ---------------------------------------------------------------------------
__global__ void __launch_bounds__(288) ctc_fused_kernel(
    const float* __restrict__ logits,
    const int* __restrict__ targets,
    const int* __restrict__ input_lengths,
    const int* __restrict__ target_lengths,
    float* __restrict__ out) {
  __shared__ float ring[4][8][68];     // compressed [eb, pad*3, p1,p3,...,p127]
  __shared__ float scratch[8][C_];     // per-producer-warp exp scratch
  __shared__ int   stg[L_];
  __shared__ float shf[132];

  int b = blockIdx.x;
  int tid = threadIdx.x;
  int wid = tid >> 5, lane = tid & 31;
  int len = input_lengths[b];
  int tl  = target_lengths[b];
  int Sb  = 2 * tl + 1;

  if (tid < L_) stg[tid] = targets[b * L_ + tid];
  __syncthreads();                                    // one block-wide barrier

  const float* lg = logits + (size_t)b * T_ * C_;

  if (wid < 8) {
    // ---------------- producers ----------------
    int t0l = stg[2 * lane], t1l = stg[2 * lane + 1];
    float c1m = (4 * lane + 1 < Sb) ? 256.f : 0.f;
    float c3m = (4 * lane + 3 < Sb) ? 256.f : 0.f;
    float* scr = scratch[wid];

#define LOADPH(PH, RA, RB)                                                 \
    do {                                                                   \
      int r_ = (PH) * 8 + wid; r_ = r_ < T_ ? r_ : T_ - 1;                 \
      const float4* p_ = (const float4*)(lg + (size_t)r_ * C_);            \
      (RA) = p_[lane]; (RB) = p_[lane + 32];                               \
    } while (0)

#define PRODUCE(VA, VB, SLOT)                                              \
    do {                                                                   \
      float4 eA, eB;                                                       \
      eA.x = __expf((VA).x); eA.y = __expf((VA).y);                        \
      eA.z = __expf((VA).z); eA.w = __expf((VA).w);                        \
      eB.x = __expf((VB).x); eB.y = __expf((VB).y);                        \
      eB.z = __expf((VB).z); eB.w = __expf((VB).w);                        \
      float s = ((eA.x + eA.y) + (eA.z + eA.w)) +                          \
                ((eB.x + eB.y) + (eB.z + eB.w));                           \
      _Pragma("unroll")                                                    \
      for (int o = 16; o; o >>= 1) s += __shfl_xor_sync(0xffffffffu, s, o);\
      float inv = __frcp_rn(s);                                            \
      ((float4*)scr)[lane]      = eA;                                      \
      ((float4*)scr)[lane + 32] = eB;                                      \
      __syncwarp();                                                        \
      float2 o2;                                                           \
      o2.x = scr[t0l] * inv * c1m;                                         \
      o2.y = scr[t1l] * inv * c3m;                                         \
      ((float2*)((SLOT) + 4))[lane] = o2;                                  \
      if (lane == 0) (SLOT)[0] = scr[0] * inv * 256.f;                     \
      __syncwarp();                                                        \
    } while (0)

    float4 aA, aB, cOA, cOB, cEA, cEB, nA, nB;
    // preamble: fill slots 0-3 (phases 0-3), staging 2 phases ahead
    LOADPH(0, aA, aB); LOADPH(1, cOA, cOB); LOADPH(2, cEA, cEB);
    PRODUCE(aA, aB, ring[0][wid]);                    BAR_ARRIVE(FULL0);
    LOADPH(3, nA, nB); PRODUCE(cOA, cOB, ring[1][wid]);
    cOA = nA; cOB = nB;                               BAR_ARRIVE(FULL1);
    LOADPH(4, nA, nB); PRODUCE(cEA, cEB, ring[2][wid]);
    cEA = nA; cEB = nB;                               BAR_ARRIVE(FULL2);
    LOADPH(5, nA, nB); PRODUCE(cOA, cOB, ring[3][wid]);
    cOA = nA; cOB = nB;                               BAR_ARRIVE(FULL3);

    for (int p = 4; p < 64; p += 4) {
      LOADPH(p + 2, nA, nB); BAR_SYNC(EMPTY0);
      PRODUCE(cEA, cEB, ring[0][wid]); cEA = nA; cEB = nB; BAR_ARRIVE(FULL0);
      LOADPH(p + 3, nA, nB); BAR_SYNC(EMPTY1);
      PRODUCE(cOA, cOB, ring[1][wid]); cOA = nA; cOB = nB; BAR_ARRIVE(FULL1);
      LOADPH(p + 4, nA, nB); BAR_SYNC(EMPTY2);
      PRODUCE(cEA, cEB, ring[2][wid]); cEA = nA; cEB = nB; BAR_ARRIVE(FULL2);
      LOADPH(p + 5, nA, nB); BAR_SYNC(EMPTY3);
      PRODUCE(cOA, cOB, ring[3][wid]); cOA = nA; cOB = nB; BAR_ARRIVE(FULL3);
    }
#undef LOADPH
#undef PRODUCE
  } else {
    // ---------------- consumer (warp 8) ----------------
    int t0l = stg[2 * lane], t1l = stg[2 * lane + 1];
    float skip1 = 0.f, skip3 = (t1l != t0l) ? 1.f : 0.f;
    if (lane > 0) skip1 = (t0l != stg[2 * lane - 1]) ? 1.f : 0.f;
    float c0 = (lane > 0 && 4 * lane < Sb) ? 1.f : 0.f;

    float a0 = 0.f, a1 = 0.f, a2 = 0.f, a3 = 0.f, a4 = 0.f;
    int e_total = 0, epend = 0;
    float fpend = 1.f;

    // u1 kept RAW off the shfl; c0 folded into n0's fmaf only (invalid/odd
    // paths are killed by PL masks), shortening the a1->a3 recurrence chain.
#define CTC_STEP(EB, PL)                                                   \
    do {                                                                   \
      float u1 = __shfl_up_sync(0xffffffffu, a3, 1);                       \
      float n0 = fmaf(u1, c0, a0) * (EB);                                  \
      float n1 = fmaf(skip1, u1, a1 + a0) * (PL).x;                        \
      float n2 = (a2 + a1) * (EB);                                         \
      float n3 = fmaf(skip3, a1, a3 + a2) * (PL).y;                        \
      float n4 = (a4 + a3) * (EB);                                         \
      a0 = n0; a1 = n1; a2 = n2; a3 = n3; a4 = n4;                         \
    } while (0)

#define CTC_RENORM_PIPE()                                                  \
    do {                                                                   \
      a0 *= fpend; a1 *= fpend; a2 *= fpend; a3 *= fpend; a4 *= fpend;     \
      e_total += epend;                                                    \
      float lm = fmaxf(fmaxf(a0, a1), fmaxf(fmaxf(a2, a3), a4));           \
      unsigned mb = __reduce_max_sync(0xffffffffu, __float_as_uint(lm));   \
      epend = (mb != 0u) ? ((int)(mb >> 23) - 127) : 0;                    \
      fpend = __int_as_float((127 - epend) << 23);                         \
    } while (0)

#define CTC_PHASE(P, SLOT)                                                 \
    do {                                                                   \
      float(*buf)[68] = ring[(SLOT)];                                      \
      float  ebv[8];                                                       \
      float2 plv[8];                                                       \
      _Pragma("unroll")                                                    \
      for (int u = 0; u < 8; u++) {                                        \
        ebv[u] = buf[u][0];                                                \
        plv[u] = ((float2*)(buf[u] + 4))[lane];                            \
      }                                                                    \
      _Pragma("unroll")                                                    \
      for (int u = 0; u < 8; u++) {                                        \
        int tt = (P) * 8 + u;                                              \
        if (tt == 0) {                                                     \
          if (lane == 0) {                                                 \
            a0 = ebv[0] * (1.f / 256.f);                                   \
            a1 = plv[0].x * (1.f / 256.f);                                 \
          }                                                                \
        } else if (tt < len) {                                             \
          CTC_STEP(ebv[u], plv[u]);                                        \
          if ((tt & 3) == 3) CTC_RENORM_PIPE();                            \
        }                                                                  \
      }                                                                    \
    } while (0)

    for (int p = 0; p < 60; p += 4) {
      BAR_SYNC(FULL0); CTC_PHASE(p + 0, 0); BAR_ARRIVE(EMPTY0);
      BAR_SYNC(FULL1); CTC_PHASE(p + 1, 1); BAR_ARRIVE(EMPTY1);
      BAR_SYNC(FULL2); CTC_PHASE(p + 2, 2); BAR_ARRIVE(EMPTY2);
      BAR_SYNC(FULL3); CTC_PHASE(p + 3, 3); BAR_ARRIVE(EMPTY3);
    }
    BAR_SYNC(FULL0); CTC_PHASE(60, 0);
    BAR_SYNC(FULL1); CTC_PHASE(61, 1);
    BAR_SYNC(FULL2); CTC_PHASE(62, 2);
    BAR_SYNC(FULL3); CTC_PHASE(63, 3);

    // per-row loss
    shf[4 * lane + 0] = a0;
    shf[4 * lane + 1] = a1;
    shf[4 * lane + 2] = a2;
    shf[4 * lane + 3] = a3;
    if (lane == 31) shf[128] = a4;
    __syncwarp();
    if (lane == 0) {
      float ssum = shf[2 * tl] + shf[2 * tl - 1];
      // a_true = a_stored * 2^(e_total - 8*(len-1))
      float loss = -(logf(ssum) +
                     (float)(e_total - 8 * (len - 1)) * 0.69314718055994530942f);
      if (!isfinite(loss) || loss > 1e20f) loss = 0.f;   // zero_infinity
      g_loss[b] = loss / (float)tl;
    }

    // fold the batch mean into the last-arriving block (replay-safe)
    __threadfence();
    unsigned tkt = 0;
    if (lane == 0) tkt = atomicAdd(&g_ctr, 1u);
    tkt = __shfl_sync(0xffffffffu, tkt, 0);
    if (tkt == B_ - 1) {
      __threadfence();
      float v = 0.f;
      #pragma unroll
      for (int j = 0; j < 8; j++) v += __ldcg(&g_loss[lane * 8 + j]);
      #pragma unroll
      for (int o = 16; o; o >>= 1) v += __shfl_xor_sync(0xffffffffu, v, o);
      if (lane == 0) {
        *out = v * (1.0f / (float)B_);
        atomicExch(&g_ctr, 0u);                        // reset for graph replay
      }
    }
#undef CTC_STEP
#undef CTC_RENORM_PIPE
#undef CTC_PHASE
  }
}

extern "C" void kernel_launch(void* const* d_in, const int* in_sizes, int n_in,
                              void* d_out, int out_size) {
  const float* logits         = (const float*)d_in[0];
  const int*   targets        = (const int*)d_in[1];
  const int*   input_lengths  = (const int*)d_in[2];
  const int*   target_lengths = (const int*)d_in[3];
  (void)in_sizes; (void)n_in; (void)out_size;

  ctc_fused_kernel<<<B_, 288>>>(logits, targets, input_lengths, target_lengths,
                                (float*)d_out);
}